// round 16
// baseline (speedup 1.0000x reference)
#include <cuda_runtime.h>

typedef unsigned long long u64;
typedef unsigned int u32;

__device__ __forceinline__ u64 pk2(float lo, float hi) {
    u64 r; asm("mov.b64 %0, {%1, %2};" : "=l"(r) : "f"(lo), "f"(hi)); return r;
}
__device__ __forceinline__ u64 dup2(float v) { return pk2(v, v); }
__device__ __forceinline__ void upk2(u64 v, float& a, float& b) {
    asm("mov.b64 {%0, %1}, %2;" : "=f"(a), "=f"(b) : "l"(v));
}
// Packed f32x2 ops (Blackwell) — 2x fp32 per issue slot.
__device__ __forceinline__ u64 fma2(u64 a, u64 b, u64 c) {
    u64 d; asm("fma.rn.f32x2 %0, %1, %2, %3;" : "=l"(d) : "l"(a), "l"(b), "l"(c)); return d;
}
__device__ __forceinline__ u64 add2(u64 a, u64 b) {
    u64 d; asm("add.rn.f32x2 %0, %1, %2;" : "=l"(d) : "l"(a), "l"(b)); return d;
}
__device__ __forceinline__ u64 mul2(u64 a, u64 b) {
    u64 d; asm("mul.rn.f32x2 %0, %1, %2;" : "=l"(d) : "l"(a), "l"(b)); return d;
}
__device__ __forceinline__ u32 smem_u32(const void* p) {
    u32 a; asm("{ .reg .u64 t; cvta.to.shared.u64 t, %1; cvt.u32.u64 %0, t; }"
               : "=r"(a) : "l"(p));
    return a;
}

#define KNN 9
#define CC 256      // channels
#define NN 256      // nodes per patch (16x16)
#define HW 12544    // 112*112

// branch-free sorted insert of key into desc-sorted bv[0..8]
__device__ __forceinline__ void ins9(u32* bv, u32 key) {
    bv[KNN - 1] = max(bv[KNN - 1], key);
    #pragma unroll
    for (int j = KNN - 1; j > 0; --j) {
        u32 lo = min(bv[j], bv[j - 1]);
        u32 hi = max(bv[j], bv[j - 1]);
        bv[j] = lo; bv[j - 1] = hi;
    }
}

// 64 threads/block; thread t owns 4 ADJACENT nodes 4t..4t+3 (same row).
// Phase 2 uses the EXACT pair-filter (one ins9 per node per m-pair, partners
// of surviving winners re-inserted bit-identically). x prefetch is issued
// before weight staging to hide the cold-start DRAM latency.
__global__ __launch_bounds__(64, 6) void gnn_fused_kernel(
    const float* __restrict__ x,
    const float* __restrict__ f_w, const float* __restrict__ f_b,
    const float* __restrict__ p_w, const float* __restrict__ p_b,
    const float* __restrict__ e_a, const float* __restrict__ e_b,
    float* __restrict__ out)
{
    __shared__ ulonglong2 wbuf[256][4];          // 16 KB weights (f_w then p_w)
    __shared__ __align__(16) char upool[16384];  // 16 KB: xs[4][1024] ring, then nodes2
    __shared__ float nrm_s[256];
    __shared__ float pb_s[256];

    ulonglong2 (*nodes2)[4] = (ulonglong2 (*)[4])upool;   // 16 KB view (post phase-1)
    float* xs = (float*)upool;                            // 4 x 1024 floats view

    const int t   = threadIdx.x;            // 0..63
    const int blk = blockIdx.x;
    const int b   = blk / 49;
    const int rr  = blk % 49;
    const int wgi = rr / 7, wgj = rr % 7;
    const int row = t >> 2;                  // 0..15
    const int col = (t & 3) * 4;             // 0,4,8,12 ; nodes 4t..4t+3 = (row, col..col+3)
    const int px  = row * 16 + col;          // = 4t: float index within a channel slab

    // ---- cp.async addressing: chunk = 4 channels x 256 pixels = 4 KB ----
    const float* xbase = x + (size_t)b * CC * HW + (size_t)(wgi * 16) * 112 + wgj * 16;
    int  soffq[4];
    u32  doffq[4];
    #pragma unroll
    for (int q = 0; q < 4; ++q) {
        int f = q * 64 + t;
        int cl = f >> 6, rem = f & 63;
        int r8 = rem >> 2, qd = rem & 3;
        soffq[q] = cl * HW + r8 * 112 + qd * 4;
        doffq[q] = (u32)f * 16u;
    }
    const u32 xs_base = smem_u32(xs);

    // ---- prologue FIRST: chunks 0..2 in flight while weights stage ----
    #pragma unroll
    for (int p = 0; p < 3; ++p) {
        const float* sp = xbase + (size_t)p * 4 * HW;
        u32 bufp = xs_base + (u32)(p * 4096);
        #pragma unroll
        for (int q = 0; q < 4; ++q) {
            asm volatile("cp.async.cg.shared.global [%0], [%1], 16;"
                         :: "r"(bufp + doffq[q]), "l"(sp + soffq[q]) : "memory");
        }
        asm volatile("cp.async.commit_group;" ::: "memory");
    }

    // ---- stage fw2[c][j] = (f_w[2j][c], f_w[2j+1][c]) : 2048 u64, 32/thread ----
    {
        u64* w = (u64*)wbuf;
        #pragma unroll
        for (int i = 0; i < 32; ++i) {
            int idx = i * 64 + t;
            int c = idx >> 3, j = idx & 7;
            w[idx] = pk2(f_w[(2 * j) * CC + c], f_w[(2 * j + 1) * CC + c]);
        }
    }
    #pragma unroll
    for (int i = 0; i < 4; ++i) pb_s[i * 64 + t] = p_b[i * 64 + t];

    u64 acc[4][8];
    #pragma unroll
    for (int j = 0; j < 8; ++j) {
        u64 fb = pk2(f_b[2 * j], f_b[2 * j + 1]);
        #pragma unroll
        for (int n = 0; n < 4; ++n) acc[n][j] = fb;
    }

    __syncthreads();   // wbuf (f_w) visible

    // ---- Phase 1: f conv via 4-buffer / depth-3 cp.async pipeline ----
    {
        #pragma unroll 1
        for (int k = 0; k < 64; ++k) {
            if (k < 62)       { asm volatile("cp.async.wait_group 2;" ::: "memory"); }
            else if (k == 62) { asm volatile("cp.async.wait_group 1;" ::: "memory"); }
            else              { asm volatile("cp.async.wait_group 0;" ::: "memory"); }
            __syncthreads();   // chunk k visible; all warps done with k-1

            if (k < 61) {
                const float* sn = xbase + (size_t)(k + 3) * 4 * HW;
                u32 bufn = xs_base + (u32)(((k + 3) & 3) * 4096);
                #pragma unroll
                for (int q = 0; q < 4; ++q) {
                    asm volatile("cp.async.cg.shared.global [%0], [%1], 16;"
                                 :: "r"(bufn + doffq[q]), "l"(sn + soffq[q]) : "memory");
                }
                asm volatile("cp.async.commit_group;" ::: "memory");
            }

            const float* xc = xs + (k & 3) * 1024;
            #pragma unroll
            for (int u = 0; u < 4; ++u) {
                float4 xv = *(const float4*)(xc + u * 256 + px);   // 4 adjacent pixels
                u64 d0 = dup2(xv.x), d1 = dup2(xv.y), d2 = dup2(xv.z), d3 = dup2(xv.w);
                #pragma unroll
                for (int j2 = 0; j2 < 4; ++j2) {
                    ulonglong2 q = wbuf[4 * k + u][j2];
                    acc[0][2 * j2]     = fma2(d0, q.x, acc[0][2 * j2]);
                    acc[0][2 * j2 + 1] = fma2(d0, q.y, acc[0][2 * j2 + 1]);
                    acc[1][2 * j2]     = fma2(d1, q.x, acc[1][2 * j2]);
                    acc[1][2 * j2 + 1] = fma2(d1, q.y, acc[1][2 * j2 + 1]);
                    acc[2][2 * j2]     = fma2(d2, q.x, acc[2][2 * j2]);
                    acc[2][2 * j2 + 1] = fma2(d2, q.y, acc[2][2 * j2 + 1]);
                    acc[3][2 * j2]     = fma2(d3, q.x, acc[3][2 * j2]);
                    acc[3][2 * j2 + 1] = fma2(d3, q.y, acc[3][2 * j2 + 1]);
                }
            }
        }
    }
    __syncthreads();   // pool becomes nodes2

    // ---- normalize all 4 nodes in registers ----
    #pragma unroll
    for (int n = 0; n < 4; ++n) {
        u64 s2 = 0ull;
        #pragma unroll
        for (int j = 0; j < 8; ++j) s2 = fma2(acc[n][j], acc[n][j], s2);
        float a0, a1; upk2(s2, a0, a1);
        float ss = a0 + a1;
        nrm_s[4 * t + n] = sqrtf(ss);
        u64 rv = dup2(rsqrtf(fmaxf(ss, 1e-24f)));
        #pragma unroll
        for (int j = 0; j < 8; ++j) acc[n][j] = mul2(acc[n][j], rv);
        ulonglong2 qa, qb;
        qa.x = acc[n][0]; qa.y = acc[n][1];
        qb.x = acc[n][2]; qb.y = acc[n][3];
        nodes2[4 * t + n][0] = qa;
        nodes2[4 * t + n][1] = qb;
        qa.x = acc[n][4]; qa.y = acc[n][5];
        qb.x = acc[n][6]; qb.y = acc[n][7];
        nodes2[4 * t + n][2] = qa;
        nodes2[4 * t + n][3] = qb;
    }

    __syncthreads();   // nodes2 visible; wbuf (f_w) reads done

    // ---- restage wbuf with RAW p_w rows ----
    {
        const float4* pw4 = (const float4*)p_w;   // 1024 float4
        float4* w4 = (float4*)wbuf;
        #pragma unroll
        for (int i = 0; i < 16; ++i) w4[i * 64 + t] = pw4[i * 64 + t];
    }
    __syncthreads();

    const u64 seed2 = pk2(2.0f, 0.0f);

    // ---- Phase 2 pass 1: pair-filtered top-9, 4 independent chains ----
    u32 bv[4][KNN];
    #pragma unroll
    for (int n = 0; n < 4; ++n)
        #pragma unroll
        for (int k = 0; k < KNN; ++k) bv[n][k] = 0u;

    #pragma unroll 1
    for (int m0 = 0; m0 < NN; m0 += 2) {
        u32 kp[4];   // running pair-winner key per node
        #pragma unroll
        for (int v = 0; v < 2; ++v) {
            const int m = m0 + v;
            u64 d0[4], d1[4];
            {
                ulonglong2 q0 = nodes2[m][0];
                ulonglong2 q1 = nodes2[m][1];
                #pragma unroll
                for (int n = 0; n < 4; ++n) {
                    d0[n] = fma2(acc[n][0], q0.x, seed2);
                    d1[n] = mul2(acc[n][1], q0.y);
                    d0[n] = fma2(acc[n][2], q1.x, d0[n]);
                    d1[n] = fma2(acc[n][3], q1.y, d1[n]);
                }
            }
            {
                ulonglong2 q2 = nodes2[m][2];
                ulonglong2 q3 = nodes2[m][3];
                #pragma unroll
                for (int n = 0; n < 4; ++n) {
                    d0[n] = fma2(acc[n][4], q2.x, d0[n]);
                    d1[n] = fma2(acc[n][5], q2.y, d1[n]);
                    d0[n] = fma2(acc[n][6], q3.x, d0[n]);
                    d1[n] = fma2(acc[n][7], q3.y, d1[n]);
                }
            }
            #pragma unroll
            for (int n = 0; n < 4; ++n) {
                u64 dd = add2(d0[n], d1[n]);
                float x0, x1; upk2(dd, x0, x1);
                float tt = fmaxf(x0 + x1, 1.0f);            // = clamp(dot,-1)+2
                u32 u = __float_as_uint(tt) - 0x3F800000u;
                u32 key = u * 256u + (u32)m;
                kp[n] = (v == 0) ? key : max(kp[n], key);
            }
        }
        #pragma unroll
        for (int n = 0; n < 4; ++n) ins9(bv[n], kp[n]);
    }

    // ---- Phase 2 pass 2: re-insert partners, 2 nodes interleaved ----
    #pragma unroll
    for (int g = 0; g < 2; ++g) {           // node pairs {0,1}, {2,3}
        const int n0 = 2 * g, n1 = 2 * g + 1;
        u32 pa0 = 0, pa1 = 0, pa2, pb0 = 0, pb1 = 0, pb2;
        #pragma unroll
        for (int k = 0; k < 4; ++k) { pa0 |= (bv[n0][k] & 255u) << (8 * k); pb0 |= (bv[n1][k] & 255u) << (8 * k); }
        #pragma unroll
        for (int k = 4; k < 8; ++k) { pa1 |= (bv[n0][k] & 255u) << (8 * (k - 4)); pb1 |= (bv[n1][k] & 255u) << (8 * (k - 4)); }
        pa2 = bv[n0][8] & 255u; pb2 = bv[n1][8] & 255u;

        #pragma unroll
        for (int k = 0; k < KNN; ++k) {
            u32 iwa = (k < 4) ? ((pa0 >> (8 * k)) & 255u)
                    : (k < 8) ? ((pa1 >> (8 * (k - 4))) & 255u) : pa2;
            u32 iwb = (k < 4) ? ((pb0 >> (8 * k)) & 255u)
                    : (k < 8) ? ((pb1 >> (8 * (k - 4))) & 255u) : pb2;
            int ipa = (int)(iwa ^ 1u);    // pair partner
            int ipb = (int)(iwb ^ 1u);
            u64 da0, da1, db0, db1;
            {
                ulonglong2 qa0 = nodes2[ipa][0];
                ulonglong2 qa1 = nodes2[ipa][1];
                da0 = fma2(acc[n0][0], qa0.x, seed2);
                da1 = mul2(acc[n0][1], qa0.y);
                da0 = fma2(acc[n0][2], qa1.x, da0);
                da1 = fma2(acc[n0][3], qa1.y, da1);
                ulonglong2 qa2 = nodes2[ipa][2];
                ulonglong2 qa3 = nodes2[ipa][3];
                da0 = fma2(acc[n0][4], qa2.x, da0);
                da1 = fma2(acc[n0][5], qa2.y, da1);
                da0 = fma2(acc[n0][6], qa3.x, da0);
                da1 = fma2(acc[n0][7], qa3.y, da1);
            }
            {
                ulonglong2 qb0 = nodes2[ipb][0];
                ulonglong2 qb1 = nodes2[ipb][1];
                db0 = fma2(acc[n1][0], qb0.x, seed2);
                db1 = mul2(acc[n1][1], qb0.y);
                db0 = fma2(acc[n1][2], qb1.x, db0);
                db1 = fma2(acc[n1][3], qb1.y, db1);
                ulonglong2 qb2 = nodes2[ipb][2];
                ulonglong2 qb3 = nodes2[ipb][3];
                db0 = fma2(acc[n1][4], qb2.x, db0);
                db1 = fma2(acc[n1][5], qb2.y, db1);
                db0 = fma2(acc[n1][6], qb3.x, db0);
                db1 = fma2(acc[n1][7], qb3.y, db1);
            }
            {
                u64 dd = add2(da0, da1);
                float x0, x1; upk2(dd, x0, x1);
                u32 u = __float_as_uint(fmaxf(x0 + x1, 1.0f)) - 0x3F800000u;
                ins9(bv[n0], u * 256u + (u32)ipa);
            }
            {
                u64 dd = add2(db0, db1);
                float y0, y1; upk2(dd, y0, y1);
                u32 u = __float_as_uint(fmaxf(y0 + y1, 1.0f)) - 0x3F800000u;
                ins9(bv[n1], u * 256u + (u32)ipb);
            }
        }
    }

    // ---- edge weights + gather: two-pass (no wn/bi arrays, low regs) ----
    const float alpha = e_a[0], beta = e_b[0];
    float iv[4];
    #pragma unroll
    for (int n = 0; n < 4; ++n) {
        float ws = 0.f;
        #pragma unroll
        for (int k = 0; k < KNN; ++k) {
            float sv = __uint_as_float((bv[n][k] >> 8) + 0x3F800000u) - 2.0f;
            ws += __fdividef(1.f, 1.f + __expf(-(beta + alpha * sv)));
        }
        iv[n] = __fdividef(1.f, ws + 1e-12f);
    }

    u64 o2[4][8];
    #pragma unroll
    for (int n = 0; n < 4; ++n)
        #pragma unroll
        for (int j = 0; j < 8; ++j) o2[n][j] = 0ull;

    #pragma unroll
    for (int k = 0; k < KNN; ++k) {
        #pragma unroll
        for (int n = 0; n < 4; ++n) {
            int idx = (int)(bv[n][k] & 255u);
            float sv = __uint_as_float((bv[n][k] >> 8) + 0x3F800000u) - 2.0f;
            float g = __fdividef(1.f, 1.f + __expf(-(beta + alpha * sv))) * iv[n] * nrm_s[idx];
            u64 ww = dup2(g);
            ulonglong2 qa = nodes2[idx][0];
            ulonglong2 qb = nodes2[idx][1];
            o2[n][0] = fma2(ww, qa.x, o2[n][0]);
            o2[n][1] = fma2(ww, qa.y, o2[n][1]);
            o2[n][2] = fma2(ww, qb.x, o2[n][2]);
            o2[n][3] = fma2(ww, qb.y, o2[n][3]);
            qa = nodes2[idx][2];
            qb = nodes2[idx][3];
            o2[n][4] = fma2(ww, qa.x, o2[n][4]);
            o2[n][5] = fma2(ww, qa.y, o2[n][5]);
            o2[n][6] = fma2(ww, qb.x, o2[n][6]);
            o2[n][7] = fma2(ww, qb.y, o2[n][7]);
        }
    }

    // ---- Phase 3: p conv (Cf=16 -> C=256), 4 adjacent pixels -> STG.128 ----
    float4* op = (float4*)(out + (size_t)b * CC * HW
                     + (size_t)((wgi * 16 + row) * 112 + wgj * 16 + col));
    #pragma unroll 2
    for (int co = 0; co < CC; ++co) {
        u64 s0[4], s1[4];
        {
            ulonglong2 q0 = wbuf[co][0];
            ulonglong2 q1 = wbuf[co][1];
            #pragma unroll
            for (int n = 0; n < 4; ++n) {
                s0[n] = mul2(q0.x, o2[n][0]);
                s1[n] = mul2(q0.y, o2[n][1]);
                s0[n] = fma2(q1.x, o2[n][2], s0[n]);
                s1[n] = fma2(q1.y, o2[n][3], s1[n]);
            }
        }
        {
            ulonglong2 q2 = wbuf[co][2];
            ulonglong2 q3 = wbuf[co][3];
            #pragma unroll
            for (int n = 0; n < 4; ++n) {
                s0[n] = fma2(q2.x, o2[n][4], s0[n]);
                s1[n] = fma2(q2.y, o2[n][5], s1[n]);
                s0[n] = fma2(q3.x, o2[n][6], s0[n]);
                s1[n] = fma2(q3.y, o2[n][7], s1[n]);
            }
        }
        float pb = pb_s[co];
        float4 o;
        { u64 r = add2(s0[0], s1[0]); float r0, r1; upk2(r, r0, r1); o.x = (r0 + r1) + pb; }
        { u64 r = add2(s0[1], s1[1]); float r0, r1; upk2(r, r0, r1); o.y = (r0 + r1) + pb; }
        { u64 r = add2(s0[2], s1[2]); float r0, r1; upk2(r, r0, r1); o.z = (r0 + r1) + pb; }
        { u64 r = add2(s0[3], s1[3]); float r0, r1; upk2(r, r0, r1); o.w = (r0 + r1) + pb; }
        op[(size_t)co * (HW / 4)] = o;
    }
}

extern "C" void kernel_launch(void* const* d_in, const int* in_sizes, int n_in,
                              void* d_out, int out_size) {
    const float* x   = (const float*)d_in[0];
    const float* f_w = (const float*)d_in[1];
    const float* f_b = (const float*)d_in[2];
    const float* p_w = (const float*)d_in[3];
    const float* p_b = (const float*)d_in[4];
    const float* e_a = (const float*)d_in[5];
    const float* e_b = (const float*)d_in[6];
    float* out = (float*)d_out;
    gnn_fused_kernel<<<784, 64>>>(x, f_w, f_b, p_w, p_b, e_a, e_b, out);
}

// round 17
// speedup vs baseline: 1.0140x; 1.0140x over previous
#include <cuda_runtime.h>

typedef unsigned long long u64;
typedef unsigned int u32;

__device__ __forceinline__ u64 pk2(float lo, float hi) {
    u64 r; asm("mov.b64 %0, {%1, %2};" : "=l"(r) : "f"(lo), "f"(hi)); return r;
}
__device__ __forceinline__ u64 dup2(float v) { return pk2(v, v); }
__device__ __forceinline__ void upk2(u64 v, float& a, float& b) {
    asm("mov.b64 {%0, %1}, %2;" : "=f"(a), "=f"(b) : "l"(v));
}
// Packed f32x2 ops (Blackwell) — 2x fp32 per issue slot.
__device__ __forceinline__ u64 fma2(u64 a, u64 b, u64 c) {
    u64 d; asm("fma.rn.f32x2 %0, %1, %2, %3;" : "=l"(d) : "l"(a), "l"(b), "l"(c)); return d;
}
__device__ __forceinline__ u64 add2(u64 a, u64 b) {
    u64 d; asm("add.rn.f32x2 %0, %1, %2;" : "=l"(d) : "l"(a), "l"(b)); return d;
}
__device__ __forceinline__ u64 mul2(u64 a, u64 b) {
    u64 d; asm("mul.rn.f32x2 %0, %1, %2;" : "=l"(d) : "l"(a), "l"(b)); return d;
}
__device__ __forceinline__ u32 smem_u32(const void* p) {
    u32 a; asm("{ .reg .u64 t; cvta.to.shared.u64 t, %1; cvt.u32.u64 %0, t; }"
               : "=r"(a) : "l"(p));
    return a;
}

#define KNN 9
#define CC 256      // channels
#define NN 256      // nodes per patch (16x16)
#define HW 12544    // 112*112

// branch-free sorted insert of key into desc-sorted bv[0..8]
__device__ __forceinline__ void ins9(u32* bv, u32 key) {
    bv[KNN - 1] = max(bv[KNN - 1], key);
    #pragma unroll
    for (int j = KNN - 1; j > 0; --j) {
        u32 lo = min(bv[j], bv[j - 1]);
        u32 hi = max(bv[j], bv[j - 1]);
        bv[j] = lo; bv[j - 1] = hi;
    }
}

// 64 threads/block; thread t owns 4 ADJACENT nodes 4t..4t+3 (same row).
// Phase 2 uses the EXACT pair-filter: one ins9 per node per m-pair (pair
// winner), then partners of surviving winners are recomputed bit-identically
// and re-inserted. Selection provably identical to the full scan.
__global__ __launch_bounds__(64, 6) void gnn_fused_kernel(
    const float* __restrict__ x,
    const float* __restrict__ f_w, const float* __restrict__ f_b,
    const float* __restrict__ p_w, const float* __restrict__ p_b,
    const float* __restrict__ e_a, const float* __restrict__ e_b,
    float* __restrict__ out)
{
    __shared__ ulonglong2 wbuf[256][4];          // 16 KB weights (f_w then p_w)
    __shared__ __align__(16) char upool[16384];  // 16 KB: xs[4][1024] ring, then nodes2
    __shared__ float nrm_s[256];
    __shared__ float pb_s[256];

    ulonglong2 (*nodes2)[4] = (ulonglong2 (*)[4])upool;   // 16 KB view (post phase-1)
    float* xs = (float*)upool;                            // 4 x 1024 floats view

    const int t   = threadIdx.x;            // 0..63
    const int blk = blockIdx.x;
    const int b   = blk / 49;
    const int rr  = blk % 49;
    const int wgi = rr / 7, wgj = rr % 7;
    const int row = t >> 2;                  // 0..15
    const int col = (t & 3) * 4;             // 0,4,8,12 ; nodes 4t..4t+3 = (row, col..col+3)
    const int px  = row * 16 + col;          // = 4t: float index within a channel slab

    // ---- stage fw2[c][j] = (f_w[2j][c], f_w[2j+1][c]) : 2048 u64, 32/thread ----
    {
        u64* w = (u64*)wbuf;
        #pragma unroll
        for (int i = 0; i < 32; ++i) {
            int idx = i * 64 + t;
            int c = idx >> 3, j = idx & 7;
            w[idx] = pk2(f_w[(2 * j) * CC + c], f_w[(2 * j + 1) * CC + c]);
        }
    }
    #pragma unroll
    for (int i = 0; i < 4; ++i) pb_s[i * 64 + t] = p_b[i * 64 + t];

    u64 acc[4][8];
    #pragma unroll
    for (int j = 0; j < 8; ++j) {
        u64 fb = pk2(f_b[2 * j], f_b[2 * j + 1]);
        #pragma unroll
        for (int n = 0; n < 4; ++n) acc[n][j] = fb;
    }

    // ---- cp.async addressing: chunk = 4 channels x 256 pixels = 4 KB ----
    const float* xbase = x + (size_t)b * CC * HW + (size_t)(wgi * 16) * 112 + wgj * 16;
    int  soffq[4];
    u32  doffq[4];
    #pragma unroll
    for (int q = 0; q < 4; ++q) {
        int f = q * 64 + t;
        int cl = f >> 6, rem = f & 63;
        int r8 = rem >> 2, qd = rem & 3;
        soffq[q] = cl * HW + r8 * 112 + qd * 4;
        doffq[q] = (u32)f * 16u;
    }
    const u32 xs_base = smem_u32(xs);

    __syncthreads();   // wbuf (f_w) visible

    // ---- Phase 1: f conv via 4-buffer / depth-3 cp.async pipeline ----
    {
        #pragma unroll
        for (int p = 0; p < 3; ++p) {
            const float* sp = xbase + (size_t)p * 4 * HW;
            u32 bufp = xs_base + (u32)(p * 4096);
            #pragma unroll
            for (int q = 0; q < 4; ++q) {
                asm volatile("cp.async.cg.shared.global [%0], [%1], 16;"
                             :: "r"(bufp + doffq[q]), "l"(sp + soffq[q]) : "memory");
            }
            asm volatile("cp.async.commit_group;" ::: "memory");
        }
        #pragma unroll 1
        for (int k = 0; k < 64; ++k) {
            if (k < 62)       { asm volatile("cp.async.wait_group 2;" ::: "memory"); }
            else if (k == 62) { asm volatile("cp.async.wait_group 1;" ::: "memory"); }
            else              { asm volatile("cp.async.wait_group 0;" ::: "memory"); }
            __syncthreads();   // chunk k visible; all warps done with k-1

            if (k < 61) {
                const float* sn = xbase + (size_t)(k + 3) * 4 * HW;
                u32 bufn = xs_base + (u32)(((k + 3) & 3) * 4096);
                #pragma unroll
                for (int q = 0; q < 4; ++q) {
                    asm volatile("cp.async.cg.shared.global [%0], [%1], 16;"
                                 :: "r"(bufn + doffq[q]), "l"(sn + soffq[q]) : "memory");
                }
                asm volatile("cp.async.commit_group;" ::: "memory");
            }

            const float* xc = xs + (k & 3) * 1024;
            // batch the 4 chunk loads up front (MLP=4 into the LSU)
            float4 xv[4];
            #pragma unroll
            for (int u = 0; u < 4; ++u)
                xv[u] = *(const float4*)(xc + u * 256 + px);
            #pragma unroll
            for (int u = 0; u < 4; ++u) {
                u64 d0 = dup2(xv[u].x), d1 = dup2(xv[u].y),
                    d2 = dup2(xv[u].z), d3 = dup2(xv[u].w);
                #pragma unroll
                for (int j2 = 0; j2 < 4; ++j2) {
                    ulonglong2 q = wbuf[4 * k + u][j2];
                    acc[0][2 * j2]     = fma2(d0, q.x, acc[0][2 * j2]);
                    acc[0][2 * j2 + 1] = fma2(d0, q.y, acc[0][2 * j2 + 1]);
                    acc[1][2 * j2]     = fma2(d1, q.x, acc[1][2 * j2]);
                    acc[1][2 * j2 + 1] = fma2(d1, q.y, acc[1][2 * j2 + 1]);
                    acc[2][2 * j2]     = fma2(d2, q.x, acc[2][2 * j2]);
                    acc[2][2 * j2 + 1] = fma2(d2, q.y, acc[2][2 * j2 + 1]);
                    acc[3][2 * j2]     = fma2(d3, q.x, acc[3][2 * j2]);
                    acc[3][2 * j2 + 1] = fma2(d3, q.y, acc[3][2 * j2 + 1]);
                }
            }
        }
    }
    __syncthreads();   // pool becomes nodes2

    // ---- normalize all 4 nodes in registers ----
    #pragma unroll
    for (int n = 0; n < 4; ++n) {
        u64 s2 = 0ull;
        #pragma unroll
        for (int j = 0; j < 8; ++j) s2 = fma2(acc[n][j], acc[n][j], s2);
        float a0, a1; upk2(s2, a0, a1);
        float ss = a0 + a1;
        nrm_s[4 * t + n] = sqrtf(ss);
        u64 rv = dup2(rsqrtf(fmaxf(ss, 1e-24f)));
        #pragma unroll
        for (int j = 0; j < 8; ++j) acc[n][j] = mul2(acc[n][j], rv);
        ulonglong2 qa, qb;
        qa.x = acc[n][0]; qa.y = acc[n][1];
        qb.x = acc[n][2]; qb.y = acc[n][3];
        nodes2[4 * t + n][0] = qa;
        nodes2[4 * t + n][1] = qb;
        qa.x = acc[n][4]; qa.y = acc[n][5];
        qb.x = acc[n][6]; qb.y = acc[n][7];
        nodes2[4 * t + n][2] = qa;
        nodes2[4 * t + n][3] = qb;
    }

    __syncthreads();   // nodes2 visible; wbuf (f_w) reads done

    // ---- restage wbuf with RAW p_w rows ----
    {
        const float4* pw4 = (const float4*)p_w;   // 1024 float4
        float4* w4 = (float4*)wbuf;
        #pragma unroll
        for (int i = 0; i < 16; ++i) w4[i * 64 + t] = pw4[i * 64 + t];
    }
    __syncthreads();

    const u64 seed2 = pk2(2.0f, 0.0f);

    // ---- Phase 2 pass 1: pair-filtered top-9, 4 independent chains ----
    u32 bv[4][KNN];
    #pragma unroll
    for (int n = 0; n < 4; ++n)
        #pragma unroll
        for (int k = 0; k < KNN; ++k) bv[n][k] = 0u;

    #pragma unroll 1
    for (int m0 = 0; m0 < NN; m0 += 2) {
        u32 kp[4];   // running pair-winner key per node
        #pragma unroll
        for (int v = 0; v < 2; ++v) {
            const int m = m0 + v;
            u64 d0[4], d1[4];
            {
                ulonglong2 q0 = nodes2[m][0];
                ulonglong2 q1 = nodes2[m][1];
                #pragma unroll
                for (int n = 0; n < 4; ++n) {
                    d0[n] = fma2(acc[n][0], q0.x, seed2);
                    d1[n] = mul2(acc[n][1], q0.y);
                    d0[n] = fma2(acc[n][2], q1.x, d0[n]);
                    d1[n] = fma2(acc[n][3], q1.y, d1[n]);
                }
            }
            {
                ulonglong2 q2 = nodes2[m][2];
                ulonglong2 q3 = nodes2[m][3];
                #pragma unroll
                for (int n = 0; n < 4; ++n) {
                    d0[n] = fma2(acc[n][4], q2.x, d0[n]);
                    d1[n] = fma2(acc[n][5], q2.y, d1[n]);
                    d0[n] = fma2(acc[n][6], q3.x, d0[n]);
                    d1[n] = fma2(acc[n][7], q3.y, d1[n]);
                }
            }
            #pragma unroll
            for (int n = 0; n < 4; ++n) {
                u64 dd = add2(d0[n], d1[n]);
                float x0, x1; upk2(dd, x0, x1);
                float tt = fmaxf(x0 + x1, 1.0f);            // = clamp(dot,-1)+2
                u32 u = __float_as_uint(tt) - 0x3F800000u;
                u32 key = u * 256u + (u32)m;
                kp[n] = (v == 0) ? key : max(kp[n], key);
            }
        }
        #pragma unroll
        for (int n = 0; n < 4; ++n) ins9(bv[n], kp[n]);
    }

    // ---- Phase 2 pass 2: re-insert partners of surviving winners ----
    // (node-sequential: snapshot 9 indices packed in 3 u32, then 9 partner
    //  re-computes with the bit-identical dot sequence)
    #pragma unroll
    for (int n = 0; n < 4; ++n) {
        u32 p0 = 0, p1 = 0, p2;
        #pragma unroll
        for (int k = 0; k < 4; ++k) p0 |= (bv[n][k] & 255u) << (8 * k);
        #pragma unroll
        for (int k = 4; k < 8; ++k) p1 |= (bv[n][k] & 255u) << (8 * (k - 4));
        p2 = bv[n][8] & 255u;

        #pragma unroll
        for (int k = 0; k < KNN; ++k) {
            u32 iw = (k < 4) ? ((p0 >> (8 * k)) & 255u)
                   : (k < 8) ? ((p1 >> (8 * (k - 4))) & 255u) : p2;
            int ip = (int)(iw ^ 1u);    // pair partner (pairs are {even, even+1})
            u64 d0, d1;
            {
                ulonglong2 q0 = nodes2[ip][0];
                ulonglong2 q1 = nodes2[ip][1];
                d0 = fma2(acc[n][0], q0.x, seed2);
                d1 = mul2(acc[n][1], q0.y);
                d0 = fma2(acc[n][2], q1.x, d0);
                d1 = fma2(acc[n][3], q1.y, d1);
            }
            {
                ulonglong2 q2 = nodes2[ip][2];
                ulonglong2 q3 = nodes2[ip][3];
                d0 = fma2(acc[n][4], q2.x, d0);
                d1 = fma2(acc[n][5], q2.y, d1);
                d0 = fma2(acc[n][6], q3.x, d0);
                d1 = fma2(acc[n][7], q3.y, d1);
            }
            u64 dd = add2(d0, d1);
            float x0, x1; upk2(dd, x0, x1);
            u32 u = __float_as_uint(fmaxf(x0 + x1, 1.0f)) - 0x3F800000u;
            ins9(bv[n], u * 256u + (u32)ip);
        }
    }

    // ---- edge weights + gather: two-pass (no wn/bi arrays, low regs) ----
    const float alpha = e_a[0], beta = e_b[0];
    float iv[4];
    #pragma unroll
    for (int n = 0; n < 4; ++n) {
        float ws = 0.f;
        #pragma unroll
        for (int k = 0; k < KNN; ++k) {
            float sv = __uint_as_float((bv[n][k] >> 8) + 0x3F800000u) - 2.0f;
            ws += __fdividef(1.f, 1.f + __expf(-(beta + alpha * sv)));
        }
        iv[n] = __fdividef(1.f, ws + 1e-12f);
    }

    u64 o2[4][8];
    #pragma unroll
    for (int n = 0; n < 4; ++n)
        #pragma unroll
        for (int j = 0; j < 8; ++j) o2[n][j] = 0ull;

    #pragma unroll
    for (int k = 0; k < KNN; ++k) {
        #pragma unroll
        for (int n = 0; n < 4; ++n) {
            int idx = (int)(bv[n][k] & 255u);
            float sv = __uint_as_float((bv[n][k] >> 8) + 0x3F800000u) - 2.0f;
            float g = __fdividef(1.f, 1.f + __expf(-(beta + alpha * sv))) * iv[n] * nrm_s[idx];
            u64 ww = dup2(g);
            ulonglong2 qa = nodes2[idx][0];
            ulonglong2 qb = nodes2[idx][1];
            o2[n][0] = fma2(ww, qa.x, o2[n][0]);
            o2[n][1] = fma2(ww, qa.y, o2[n][1]);
            o2[n][2] = fma2(ww, qb.x, o2[n][2]);
            o2[n][3] = fma2(ww, qb.y, o2[n][3]);
            qa = nodes2[idx][2];
            qb = nodes2[idx][3];
            o2[n][4] = fma2(ww, qa.x, o2[n][4]);
            o2[n][5] = fma2(ww, qa.y, o2[n][5]);
            o2[n][6] = fma2(ww, qb.x, o2[n][6]);
            o2[n][7] = fma2(ww, qb.y, o2[n][7]);
        }
    }

    // ---- Phase 3: p conv (Cf=16 -> C=256), 4 adjacent pixels -> STG.128 ----
    float4* op = (float4*)(out + (size_t)b * CC * HW
                     + (size_t)((wgi * 16 + row) * 112 + wgj * 16 + col));
    #pragma unroll 2
    for (int co = 0; co < CC; ++co) {
        u64 s0[4], s1[4];
        {
            ulonglong2 q0 = wbuf[co][0];
            ulonglong2 q1 = wbuf[co][1];
            #pragma unroll
            for (int n = 0; n < 4; ++n) {
                s0[n] = mul2(q0.x, o2[n][0]);
                s1[n] = mul2(q0.y, o2[n][1]);
                s0[n] = fma2(q1.x, o2[n][2], s0[n]);
                s1[n] = fma2(q1.y, o2[n][3], s1[n]);
            }
        }
        {
            ulonglong2 q2 = wbuf[co][2];
            ulonglong2 q3 = wbuf[co][3];
            #pragma unroll
            for (int n = 0; n < 4; ++n) {
                s0[n] = fma2(q2.x, o2[n][4], s0[n]);
                s1[n] = fma2(q2.y, o2[n][5], s1[n]);
                s0[n] = fma2(q3.x, o2[n][6], s0[n]);
                s1[n] = fma2(q3.y, o2[n][7], s1[n]);
            }
        }
        float pb = pb_s[co];
        float4 o;
        { u64 r = add2(s0[0], s1[0]); float r0, r1; upk2(r, r0, r1); o.x = (r0 + r1) + pb; }
        { u64 r = add2(s0[1], s1[1]); float r0, r1; upk2(r, r0, r1); o.y = (r0 + r1) + pb; }
        { u64 r = add2(s0[2], s1[2]); float r0, r1; upk2(r, r0, r1); o.z = (r0 + r1) + pb; }
        { u64 r = add2(s0[3], s1[3]); float r0, r1; upk2(r, r0, r1); o.w = (r0 + r1) + pb; }
        op[(size_t)co * (HW / 4)] = o;
    }
}

extern "C" void kernel_launch(void* const* d_in, const int* in_sizes, int n_in,
                              void* d_out, int out_size) {
    const float* x   = (const float*)d_in[0];
    const float* f_w = (const float*)d_in[1];
    const float* f_b = (const float*)d_in[2];
    const float* p_w = (const float*)d_in[3];
    const float* p_b = (const float*)d_in[4];
    const float* e_a = (const float*)d_in[5];
    const float* e_b = (const float*)d_in[6];
    float* out = (float*)d_out;
    gnn_fused_kernel<<<784, 64>>>(x, f_w, f_b, p_w, p_b, e_a, e_b, out);
}